// round 2
// baseline (speedup 1.0000x reference)
#include <cuda_runtime.h>
#include <cstdint>

// Problem constants (fixed-shape problem)
#define QD 50      // qubits
#define SD 64      // heads
#define SP 32      // s-pairs (SD/2), packed 2 heads per f32x2
#define CQ 10      // q per staged chunk
#define NCH 5      // chunks (QD/CQ)
#define BT 128     // block threads
#define ROWW 31    // padded smem row stride in floats (CQ*3=30 -> 31, odd = conflict-free)
#define EPSF 1e-12f

// -------- scratch (no allocation allowed; __device__ globals) --------
__device__ __align__(16) float g_headsPacked[QD * SP * 4]; // [q][s_pair]{h0e,h0o,h1e,h1o}
__device__ __align__(16) float g_w[SD];                    // hr_s * rho_s
__device__ float g_partials[4096];                         // per-CTA partial sums

typedef unsigned long long ull;

// -------- f32x2 packed math (sm_100+ PTX; FFMA2 in SASS) --------
__device__ __forceinline__ ull fma2(ull a, ull b, ull c) {
    ull d;
    asm("fma.rn.f32x2 %0, %1, %2, %3;" : "=l"(d) : "l"(a), "l"(b), "l"(c));
    return d;
}
__device__ __forceinline__ ull mul2(ull a, ull b) {
    ull d;
    asm("mul.rn.f32x2 %0, %1, %2;" : "=l"(d) : "l"(a), "l"(b));
    return d;
}
__device__ __forceinline__ ull bcast2(float x) {
    ull d;
    asm("mov.b64 %0, {%1, %1};" : "=l"(d) : "f"(x));
    return d;
}
__device__ __forceinline__ float2 unpack2(ull v) {
    float2 r;
    asm("mov.b64 {%0, %1}, %2;" : "=f"(r.x), "=f"(r.y) : "l"(v));
    return r;
}

__device__ __forceinline__ float softplus20(float x) {
    float z = 20.0f * x;
    return (z > 20.0f) ? z : log1pf(expf(z));
}

// =====================================================================
// Kernel 1: preprocess heads + head ratios (1 CTA x 1024 threads)
//   Reference divides by max(sum,EPS); we factor the clamp as a per-(s,q)
//   scale sigma = min(1, sum/EPS) and fold rho_s = prod_q sigma into the
//   head-ratio weight, so the mainloop can use the exact-sum-1 identity
//   dot = b2 + h0*(b0-b2) + h1*(b1-b2).
// =====================================================================
__global__ void __launch_bounds__(1024)
prep_kernel(const float* __restrict__ hp, const float* __restrict__ hrp) {
    __shared__ float s_sigma[SD * QD];
    __shared__ float s_sp[SD];
    __shared__ float s_tot;
    int tid = threadIdx.x;

    for (int idx = tid; idx < SD * QD; idx += 1024) {
        int s = idx / QD, q = idx - s * QD;
        const float* h = hp + (size_t)(s * QD + q) * 3;
        float h0 = softplus20(h[0]);
        float h1 = softplus20(h[1]);
        float h2 = softplus20(h[2]);
        float sum3 = h0 + h1 + h2;
        float sigma, g0, g1;
        if (sum3 > 0.0f) {
            sigma = fminf(1.0f, sum3 * 1e12f);
            g0 = h0 / sum3;
            g1 = h1 / sum3;
        } else {
            sigma = 0.0f; g0 = 0.0f; g1 = 0.0f;  // head contributes 0 (matches ref)
        }
        s_sigma[idx] = sigma;
        int base = (q * SP + (s >> 1)) * 4;
        int o = s & 1;
        g_headsPacked[base + o]     = g0;
        g_headsPacked[base + 2 + o] = g1;
    }
    if (tid < SD) s_sp[tid] = softplus20(hrp[tid]);
    __syncthreads();
    if (tid == 0) {
        float t = 0.0f;
        for (int s = 0; s < SD; s++) t += s_sp[s];
        s_tot = t;
    }
    __syncthreads();
    if (tid < SD) {
        float w = s_sp[tid] / fmaxf(s_tot, EPSF);
        w = (w + 0.001f / (float)SD) / 1.001f;
        float rho = 1.0f;
        for (int q = 0; q < QD; q++) rho *= s_sigma[tid * QD + q];
        g_w[tid] = w * rho;
    }
}

// =====================================================================
// Kernel 2: main — one n per thread, 64 heads packed as 32 f32x2 lanes.
// Batch rows are staged through smem in q-chunks so global loads are
// coalesced (contiguous 120B runs) instead of 600B-strided scalar reads.
// Inner step: 1 LDS.128 + 3 FFMA2-class ops. FMA-pipe bound by design.
// =====================================================================
__global__ void __launch_bounds__(BT)
main_kernel(const float* __restrict__ bp, const float* __restrict__ coeff, int N) {
    __shared__ ulonglong2 sH[QD * SP];     // 25.6 KB (packed heads)
    __shared__ float sB[BT * ROWW];        // 15.9 KB (staged batch chunk, padded rows)
    __shared__ ull sW[SP];
    __shared__ float s_warp[4];
    int tid = threadIdx.x;
    int n0 = blockIdx.x * BT;
    int n = n0 + tid;

    // stage packed heads into smem (broadcast-read later)
    {
        const float4* gH = (const float4*)g_headsPacked;
        float4* sH4 = (float4*)sH;
        for (int i = tid; i < QD * SP; i += BT) sH4[i] = gH[i];
        if (tid < SP) sW[tid] = ((const ull*)g_w)[tid];  // {w_even, w_odd}
    }

    ull prod[SP];
    #pragma unroll
    for (int i = 0; i < SP; i++) prod[i] = 0x3f8000003f800000ull; // {1.f,1.f}

    for (int ch = 0; ch < NCH; ch++) {
        __syncthreads();  // prev chunk consumed (also covers head staging)
        // cooperative coalesced load of this CTA's rows, q-chunk [ch*CQ, ch*CQ+CQ)
        #pragma unroll 1
        for (int j = tid; j < BT * (CQ * 3); j += BT) {
            int r = j / (CQ * 3);
            int o = j - r * (CQ * 3);
            int row = n0 + r;
            if (row < N)
                sB[r * ROWW + o] = bp[(size_t)row * (QD * 3) + ch * (CQ * 3) + o];
        }
        __syncthreads();

        if (n < N) {
            const float* myb = sB + tid * ROWW;
            #pragma unroll
            for (int qi = 0; qi < CQ; qi++) {
                float b0 = myb[3 * qi + 0];
                float b1 = myb[3 * qi + 1];
                float b2 = myb[3 * qi + 2];
                ull d0p = bcast2(b0 - b2);
                ull d1p = bcast2(b1 - b2);
                ull b2p = bcast2(b2);
                const ulonglong2* hq = sH + (ch * CQ + qi) * SP;
                #pragma unroll
                for (int i = 0; i < SP; i++) {
                    ulonglong2 h = hq[i];                 // LDS.128: {h0pair, h1pair}
                    ull m = fma2(h.x, d0p, b2p);          // b2 + h0*(b0-b2)
                    m = fma2(h.y, d1p, m);                //    + h1*(b1-b2)
                    prod[i] = mul2(prod[i], m);           // running product over q
                }
            }
        }
    }

    float contrib = 0.0f;
    if (n < N) {
        ull acc = 0ull;                                   // {0.f, 0.f}
        #pragma unroll
        for (int i = 0; i < SP; i++) acc = fma2(prod[i], sW[i], acc);
        float2 a = unpack2(acc);
        float cov = a.x + a.y;
        float c = coeff[n];
        contrib = c * c / cov;
    }

    // block reduction (deterministic order)
    #pragma unroll
    for (int o = 16; o > 0; o >>= 1)
        contrib += __shfl_down_sync(0xffffffffu, contrib, o);
    if ((tid & 31) == 0) s_warp[tid >> 5] = contrib;
    __syncthreads();
    if (tid == 0)
        g_partials[blockIdx.x] = (s_warp[0] + s_warp[1]) + (s_warp[2] + s_warp[3]);
}

// =====================================================================
// Kernel 3: deterministic final reduction over CTA partials
// =====================================================================
__global__ void reduce_kernel(float* __restrict__ out, int nb) {
    __shared__ float sh[256];
    int tid = threadIdx.x;
    float v = 0.0f;
    for (int i = tid; i < nb; i += 256) v += g_partials[i];
    sh[tid] = v;
    __syncthreads();
    for (int s = 128; s > 0; s >>= 1) {
        if (tid < s) sh[tid] += sh[tid + s];
        __syncthreads();
    }
    if (tid == 0) out[0] = sh[0];
}

extern "C" void kernel_launch(void* const* d_in, const int* in_sizes, int n_in,
                              void* d_out, int out_size) {
    const float* bp    = (const float*)d_in[0];  // batch_pauli_tensor [N,Q,3]
    const float* coeff = (const float*)d_in[1];  // batch_coeff [N]
    const float* hp    = (const float*)d_in[2];  // heads_param [S,Q,3]
    const float* hrp   = (const float*)d_in[3];  // head_ratios_param [S]
    int N = in_sizes[1];

    prep_kernel<<<1, 1024>>>(hp, hrp);
    int nb = (N + BT - 1) / BT;
    if (nb > 4096) nb = 4096;  // g_partials bound (N=100000 -> 782)
    main_kernel<<<nb, BT>>>(bp, coeff, N);
    reduce_kernel<<<1, 256>>>((float*)d_out, nb);
}

// round 8
// speedup vs baseline: 1.4991x; 1.4991x over previous
#include <cuda_runtime.h>
#include <cstdint>

// Problem constants (fixed-shape problem)
#define QD 50        // qubits
#define SD 64        // heads
#define SP 32        // s-pairs (SD/2), packed 2 heads per f32x2
#define HP 16        // pairs handled per thread (SP/2)
#define BT 64        // block threads
#define RPB 32       // rows per block (2 threads per row)
#define ROWF (QD*3)  // 150 floats per row (unpadded; smem mirrors gmem layout)
#define NPCTA 740    // persistent CTAs (148 SMs x 5)
#define MAXBLK 8192
#define EPSF 1e-12f

__device__ float g_partials[MAXBLK];   // 2 slots per block (one per warp)
__device__ int   g_ctr = 0;            // work-stealing cursor (reset by reduce_kernel)

typedef unsigned long long ull;

// -------- f32x2 packed math (sm_100+ PTX; FFMA2-class in SASS) --------
__device__ __forceinline__ ull fma2(ull a, ull b, ull c) {
    ull d;
    asm("fma.rn.f32x2 %0, %1, %2, %3;" : "=l"(d) : "l"(a), "l"(b), "l"(c));
    return d;
}
__device__ __forceinline__ ull mul2(ull a, ull b) {
    ull d;
    asm("mul.rn.f32x2 %0, %1, %2;" : "=l"(d) : "l"(a), "l"(b));
    return d;
}
__device__ __forceinline__ ull bcast2(float x) {
    ull d;
    asm("mov.b64 %0, {%1, %1};" : "=l"(d) : "f"(x));
    return d;
}
__device__ __forceinline__ float2 unpack2(ull v) {
    float2 r;
    asm("mov.b64 {%0, %1}, %2;" : "=f"(r.x), "=f"(r.y) : "l"(v));
    return r;
}
__device__ __forceinline__ float softplus20(float x) {
    float z = 20.0f * x;
    return (z > 20.0f) ? z : log1pf(expf(z));
}

// =====================================================================
// Fused persistent kernel. SMEM budget: 19.2KB dynamic (batch block)
// + ~26KB static (heads etc) = ~45.4KB < 48KB -> NO attribute call.
//
// Math identity (exact): heads are L1-normalized over p, so
//   dot = b2 + h0*(b0-b2) + h1*(b1-b2)
// with the reference's max(sum,EPS) clamp factored out as a per-(s,q)
// scale sigma = min(1, sum/EPS) whose product rho_s is folded into the
// head-ratio weight w_s.
//
// Row split: 2 threads per row; thread (tid&1)==h owns s-pairs {2i+h},
// i=0..15 -> prod[16] (32 regs), no barrier inside the accumulation.
// Determinism: g_partials[2*blk+warp] depends only on (blk,warp); final
// reduce sums slots in fixed index order, so the work-stealing schedule
// is observationally irrelevant. g_ctr is reset by reduce_kernel so
// graph replays see identical state.
// =====================================================================
__global__ void __launch_bounds__(BT)
main_kernel(const float* __restrict__ bp, const float* __restrict__ coeff,
            const float* __restrict__ hp, const float* __restrict__ hrp,
            int N, int nblk) {
    extern __shared__ float sB[];                    // dynamic: RPB*ROWF floats (19.2KB)
    __shared__ ulonglong2 sH[QD * SP];               // 25.6KB packed heads [q][pair]{h0p,h1p}
    __shared__ __align__(16) float sWf[SD];          // w_s * rho_s (read as ull pairs)
    __shared__ float s_sp[SD];
    __shared__ float s_tot;
    __shared__ int   s_blk;
    int tid = threadIdx.x;
    float* sHf = (float*)sH;

    // ---- Phase A: softplus + L1-normalize heads; sigma parked in sB ----
    for (int idx = tid; idx < SD * QD; idx += BT) {
        int s = idx / QD, q = idx - s * QD;
        const float* h = hp + (size_t)(s * QD + q) * 3;
        float h0 = softplus20(h[0]);
        float h1 = softplus20(h[1]);
        float h2 = softplus20(h[2]);
        float sum3 = h0 + h1 + h2;
        float sigma, g0, g1;
        if (sum3 > 0.0f) {
            sigma = fminf(1.0f, sum3 * 1e12f);
            g0 = h0 / sum3;
            g1 = h1 / sum3;
        } else {
            sigma = 0.0f; g0 = 0.0f; g1 = 0.0f;       // head contributes 0 (matches ref)
        }
        sB[idx] = sigma;                               // temp use of dynamic smem (12.8KB<19.2KB)
        int base = (q * SP + (s >> 1)) * 4;
        int o = s & 1;
        sHf[base + o]     = g0;                        // {h0_e,h0_o,h1_e,h1_o}
        sHf[base + 2 + o] = g1;
    }
    s_sp[tid] = softplus20(hrp[tid]);                  // BT == SD == 64
    __syncthreads();
    if (tid == 0) {
        float t = 0.0f;
        for (int s = 0; s < SD; s++) t += s_sp[s];
        s_tot = t;
    }
    __syncthreads();
    {
        float w = s_sp[tid] / fmaxf(s_tot, EPSF);
        w = (w + 0.001f / (float)SD) / 1.001f;
        float rho = 1.0f;
        for (int q = 0; q < QD; q++) rho *= sB[tid * QD + q];
        sWf[tid] = w * rho;
    }
    const ull* sW = (const ull*)sWf;

    int half = tid & 1;                                // which s-pair subset
    int myrow = tid >> 1;                              // row within block

    // ---- Phase B: work-stealing mainloop over 32-row blocks ----
    for (;;) {
        if (tid == 0) s_blk = atomicAdd(&g_ctr, 1);
        __syncthreads();                               // also: prev block's sB reads done
        int blk = s_blk;
        if (blk >= nblk) break;

        int n0 = blk * RPB;
        int nvalid = N - n0; if (nvalid > RPB) nvalid = RPB;
        int nf = nvalid * ROWF;

        // stage: contiguous gmem run; 19200*blk bytes is always 16B-aligned
        {
            const float4* src4 = (const float4*)(bp + (size_t)n0 * ROWF);
            float4* dst4 = (float4*)sB;
            int n4 = nf >> 2;                          // 1200 when full block
            for (int j = tid; j < n4; j += BT) dst4[j] = src4[j];
            for (int j = (n4 << 2) + tid; j < nf; j += BT)   // generic tail (empty when full)
                sB[j] = bp[(size_t)n0 * ROWF + j];
        }
        __syncthreads();

        float contrib = 0.0f;
        if (myrow < nvalid) {
            const float* myb = sB + myrow * ROWF;
            ull prod[HP];
            #pragma unroll
            for (int i = 0; i < HP; i++) prod[i] = 0x3f8000003f800000ull; // {1,1}

            #pragma unroll 2
            for (int q = 0; q < QD; q++) {
                float b0 = myb[3 * q + 0];
                float b1 = myb[3 * q + 1];
                float b2 = myb[3 * q + 2];
                ull d0p = bcast2(b0 - b2);
                ull d1p = bcast2(b1 - b2);
                ull b2p = bcast2(b2);
                const ulonglong2* hq = sH + q * SP + half;   // pairs {2i+half}
                #pragma unroll
                for (int i = 0; i < HP; i++) {
                    ulonglong2 h = hq[2 * i];          // LDS.128, 2 adjacent addrs/warp
                    ull m = fma2(h.x, d0p, b2p);       // b2 + h0*(b0-b2)
                    m = fma2(h.y, d1p, m);             //    + h1*(b1-b2)
                    prod[i] = mul2(prod[i], m);        // running product over q
                }
            }

            ull acc = 0ull;
            #pragma unroll
            for (int i = 0; i < HP; i++) acc = fma2(prod[i], sW[2 * i + half], acc);
            float2 a = unpack2(acc);
            float cov_half = a.x + a.y;                // this thread's 32 heads
            float cov = cov_half + __shfl_xor_sync(0xffffffffu, cov_half, 1);
            if (half == 0) {                           // count each row once
                float c = coeff[n0 + myrow];
                contrib = c * c / cov;
            }
        }

        // per-warp reduce; each warp owns its own partial slot (no cross-warp sync)
        #pragma unroll
        for (int o = 16; o > 0; o >>= 1)
            contrib += __shfl_down_sync(0xffffffffu, contrib, o);
        if ((tid & 31) == 0)
            g_partials[2 * blk + (tid >> 5)] = contrib;
    }
}

// =====================================================================
// Final deterministic reduction (fixed index order) + cursor reset
// =====================================================================
__global__ void reduce_kernel(float* __restrict__ out, int nslot) {
    __shared__ float sh[256];
    int tid = threadIdx.x;
    float v = 0.0f;
    for (int i = tid; i < nslot; i += 256) v += g_partials[i];
    sh[tid] = v;
    __syncthreads();
    for (int s = 128; s > 0; s >>= 1) {
        if (tid < s) sh[tid] += sh[tid + s];
        __syncthreads();
    }
    if (tid == 0) {
        out[0] = sh[0];
        g_ctr = 0;                   // restore invariant for next launch / graph replay
    }
}

extern "C" void kernel_launch(void* const* d_in, const int* in_sizes, int n_in,
                              void* d_out, int out_size) {
    const float* bp    = (const float*)d_in[0];  // batch_pauli_tensor [N,Q,3]
    const float* coeff = (const float*)d_in[1];  // batch_coeff [N]
    const float* hp    = (const float*)d_in[2];  // heads_param [S,Q,3]
    const float* hrp   = (const float*)d_in[3];  // head_ratios_param [S]
    int N = in_sizes[1];

    int nblk = (N + RPB - 1) / RPB;              // 3125 for N=100000
    if (nblk > MAXBLK / 2) nblk = MAXBLK / 2;
    int smem = RPB * ROWF * sizeof(float);       // 19,200B dynamic; total < 48KB

    main_kernel<<<NPCTA, BT, smem>>>(bp, coeff, hp, hrp, N, nblk);
    reduce_kernel<<<1, 256>>>((float*)d_out, 2 * nblk);
}